// round 3
// baseline (speedup 1.0000x reference)
#include <cuda_runtime.h>
#include <cuda_bf16.h>
#include <cstdint>

#define S 4096
#define GRID 128
#define BLOCK 512
#define NWARP 16
#define RPB 32             // rows per block
#define RPG 8              // rows per warp row-group
#define KQ 1024            // K-window per warp (quarter of S)
#define ROWSTRIDE (S / 8)  // uint4 per row

// ---------------- device-global scratch ----------------
static __device__ __nv_bfloat16 g_M[(size_t)S * S];     // exp(log_trans), bf16
static __device__ float g_w[2][S];                      // ping-pong unnormalized filter
static __device__ unsigned long long g_flag[2][GRID];   // ping-pong {f32 partialZ:hi, u32 gen:lo}

// ---------------- prep: M = bf16(exp(log_trans)); reset flags ----------------
__global__ void hmm_prep_kernel(const float* __restrict__ log_trans) {
    size_t gtid = (size_t)blockIdx.x * blockDim.x + threadIdx.x;
    if (gtid < 2 * GRID) g_flag[gtid / GRID][gtid % GRID] = 0ull;
    const size_t n4 = (size_t)S * S / 4;
    const size_t stride = (size_t)gridDim.x * blockDim.x;
    for (size_t i = gtid; i < n4; i += stride) {
        float4 v = reinterpret_cast<const float4*>(log_trans)[i];
        __nv_bfloat162 lo, hi;
        lo.x = __float2bfloat16(__expf(v.x));
        lo.y = __float2bfloat16(__expf(v.y));
        hi.x = __float2bfloat16(__expf(v.z));
        hi.y = __float2bfloat16(__expf(v.w));
        reinterpret_cast<__nv_bfloat162*>(g_M)[2 * i]     = lo;
        reinterpret_cast<__nv_bfloat162*>(g_M)[2 * i + 1] = hi;
    }
}

// ---------------- helpers ----------------
__device__ __forceinline__ float warp_sum(float v) {
#pragma unroll
    for (int o = 16; o; o >>= 1) v += __shfl_xor_sync(0xffffffffu, v, o);
    return v;
}

// bf16x2 (u32) -> packed f32x2 (u64): exact
__device__ __forceinline__ unsigned long long cvt2(unsigned u) {
    unsigned lo = u << 16;
    unsigned hi = u & 0xffff0000u;
    unsigned long long r;
    asm("mov.b64 %0, {%1, %2};" : "=l"(r) : "r"(lo), "r"(hi));
    return r;
}

// packed dual FMA (FFMA2)
__device__ __forceinline__ unsigned long long fma2(unsigned long long a,
                                                   unsigned long long b,
                                                   unsigned long long c) {
    unsigned long long d;
    asm("fma.rn.f32x2 %0, %1, %2, %3;" : "=l"(d) : "l"(a), "l"(b), "l"(c));
    return d;
}

__device__ __forceinline__ float f32x2_hsum(unsigned long long v) {
    unsigned lo, hi;
    asm("mov.b64 {%0, %1}, %2;" : "=r"(lo), "=r"(hi) : "l"(v));
    return __uint_as_float(lo) + __uint_as_float(hi);
}

__device__ __forceinline__ unsigned long long ldacq(const unsigned long long* p) {
    unsigned long long v;
    asm volatile("ld.acquire.gpu.global.b64 %0, [%1];" : "=l"(v) : "l"(p) : "memory");
    return v;
}
__device__ __forceinline__ void strel(unsigned long long* p, unsigned long long v) {
    asm volatile("st.release.gpu.global.b64 [%0], %1;" :: "l"(p), "l"(v) : "memory");
}
__device__ __forceinline__ void strelax(float* p, float v) {
    asm volatile("st.relaxed.gpu.global.f32 [%0], %1;" :: "l"(p), "f"(v) : "memory");
}

// Barrier + Z-reduce in one hop. Every warp polls all 128 flags of slot
// (gen & 1); exact-match is safe because the slot is rewritten (gen+2) only
// after every warp everywhere exited poll(gen) — ping-pong guarantees it.
// All 4 watched flags are re-read each pass (parallel latency, not serial).
__device__ __forceinline__ float poll_flags(unsigned gen, int lane) {
    const unsigned long long* base = g_flag[gen & 1];
    unsigned long long x0, x1, x2, x3;
    for (;;) {
        x0 = ldacq(base + lane);
        x1 = ldacq(base + lane + 32);
        x2 = ldacq(base + lane + 64);
        x3 = ldacq(base + lane + 96);
        if (((unsigned)x0 == gen) & ((unsigned)x1 == gen) &
            ((unsigned)x2 == gen) & ((unsigned)x3 == gen)) break;
    }
    float zsum = __uint_as_float((unsigned)(x0 >> 32)) +
                 __uint_as_float((unsigned)(x1 >> 32)) +
                 __uint_as_float((unsigned)(x2 >> 32)) +
                 __uint_as_float((unsigned)(x3 >> 32));
    return warp_sum(zsum);
}

// dot products: 8 rows x 1024-wide K window against smem w
template <bool CACHED>
__device__ __forceinline__ void dot8(const uint4* __restrict__ A,
                                     const float* __restrict__ swq,
                                     int lane, unsigned long long* acc) {
#pragma unroll
    for (int c = 0; c < 4; ++c) {
        const int kb = c * 32 + lane;  // uint4 index in window
        const ulonglong2 w01 = *reinterpret_cast<const ulonglong2*>(swq + c * 256 + lane * 8);
        const ulonglong2 w23 = *reinterpret_cast<const ulonglong2*>(swq + c * 256 + lane * 8 + 4);
#pragma unroll
        for (int r = 0; r < 8; ++r) {
            uint4 a;
            if (CACHED) {
                a = A[r * ROWSTRIDE + kb];
            } else {
                float4 t = __ldcg(reinterpret_cast<const float4*>(A) + r * ROWSTRIDE + kb);
                a = *reinterpret_cast<uint4*>(&t);
            }
            acc[r] = fma2(cvt2(a.x), w01.x, acc[r]);
            acc[r] = fma2(cvt2(a.y), w01.y, acc[r]);
            acc[r] = fma2(cvt2(a.z), w23.x, acc[r]);
            acc[r] = fma2(cvt2(a.w), w23.y, acc[r]);
        }
    }
}

// ---------------- persistent forward-filter kernel ----------------
__global__ void __launch_bounds__(BLOCK, 1) hmm_main_kernel(
    const float* __restrict__ log_M0,
    const float* __restrict__ log_emit,
    const int*   __restrict__ Tptr,
    float*       __restrict__ out)
{
    __shared__ float sw[S];                       // current w (linear space)
    __shared__ __align__(16) float s_red[RPB][4]; // per-(row, K-quarter) partials

    const int tid  = threadIdx.x;
    const int lane = tid & 31;
    const int warp = tid >> 5;
    const int g    = warp >> 2;   // row group 0..3
    const int q    = warp & 3;    // K quarter 0..3
    const int bid  = blockIdx.x;
    const int T    = *Tptr;

    const int r0 = bid * RPB;                     // block's first global row
    const uint4* A = reinterpret_cast<const uint4*>(
        g_M + (size_t)(r0 + g * RPG) * S + q * KQ);
    const float* swq = sw + q * KQ;

    // ---- t = 0: w0 = exp(log_M0 + log_emit[0]) for this block's 32 rows ----
    if (warp == 0) {
        int row = r0 + lane;
        float v = __expf(__ldcg(log_M0 + row) + __ldcg(log_emit + row));
        strelax(&g_w[0][row], v);
        float part = warp_sum(v);
        __syncwarp();
        if (lane == 0)
            strel(&g_flag[1][bid],
                  ((unsigned long long)__float_as_uint(part) << 32) | 1u);
    }

    double lik = 0.0;
    float Z = poll_flags(1u, lane);   // gen 1 -> slot 1
    if (bid == 0 && tid == 0) lik += (double)logf(Z);
    float invZ = 1.0f / Z;

    for (int t = 1; t <= T; ++t) {
        const int cur = t & 1, prev = cur ^ 1;
        const unsigned gen = (unsigned)(t + 1);

        // emit prefetch (overlaps with w broadcast)
        float em = 0.f;
        if (warp == 0) em = __ldcg(log_emit + (size_t)t * S + r0 + lane);

        // broadcast w_{t-1} into smem (each warp copies its 1/16 slice, L2-direct)
        {
            int j = warp * 64 + lane;
            float4 a = __ldcg(reinterpret_cast<const float4*>(g_w[prev]) + j);
            reinterpret_cast<float4*>(sw)[j] = a;
            j += 32;
            float4 b = __ldcg(reinterpret_cast<const float4*>(g_w[prev]) + j);
            reinterpret_cast<float4*>(sw)[j] = b;
        }
        __syncthreads();

        unsigned long long acc[8] = {0ull, 0ull, 0ull, 0ull, 0ull, 0ull, 0ull, 0ull};
        if (g < 3) dot8<true >(A, swq, lane, acc);
        else       dot8<false>(A, swq, lane, acc);

#pragma unroll
        for (int r = 0; r < 8; ++r) {
            float s = warp_sum(f32x2_hsum(acc[r]));
            if (lane == 0) s_red[g * RPG + r][q] = s;
        }
        __syncthreads();

        // epilogue: warp 0 finishes 32 rows, publishes segment + flag (ping-pong slot)
        if (warp == 0) {
            float4 p = *reinterpret_cast<const float4*>(s_red[lane]);
            float dot = (p.x + p.y) + (p.z + p.w);
            float v = dot * __expf(em) * invZ;
            strelax(&g_w[cur][r0 + lane], v);
            float part = warp_sum(v);
            __syncwarp();
            if (lane == 0)
                strel(&g_flag[gen & 1][bid],
                      ((unsigned long long)__float_as_uint(part) << 32) | gen);
        }

        // barrier + Z_t in one hop
        Z = poll_flags(gen, lane);
        if (bid == 0 && tid == 0) lik += (double)logf(Z);
        invZ = 1.0f / Z;
    }

    if (bid == 0 && tid == 0) out[0] = (float)lik;
}

// ---------------- launch ----------------
extern "C" void kernel_launch(void* const* d_in, const int* in_sizes, int n_in,
                              void* d_out, int out_size) {
    const float* log_M0    = (const float*)d_in[0];
    const float* log_trans = (const float*)d_in[1];
    const float* log_emit  = (const float*)d_in[2];
    const int*   Tptr      = (const int*)d_in[3];
    float* out = (float*)d_out;

    hmm_prep_kernel<<<2048, 256>>>(log_trans);
    hmm_main_kernel<<<GRID, BLOCK>>>(log_M0, log_emit, Tptr, out);
}

// round 4
// speedup vs baseline: 2.7372x; 2.7372x over previous
#include <cuda_runtime.h>
#include <cuda_bf16.h>
#include <cstdint>

#define S 4096
#define GRID 128
#define BLOCK 512
#define NWARP 16
#define RPB 32             // rows per block
#define RPG 8              // rows per warp row-group
#define KQ 1024            // K-window per warp (quarter of S)
#define ROWSTRIDE (S / 8)  // uint4 per row

// ---------------- device-global scratch ----------------
static __device__ __nv_bfloat16 g_M[(size_t)S * S];     // exp(log_trans), bf16
static __device__ float g_w[2][S];                      // ping-pong unnormalized filter
static __device__ unsigned long long g_flag[2][GRID];   // ping-pong {f32 partialZ:hi, u32 gen:lo}

// ---------------- prep: M = bf16(exp(log_trans)); reset flags ----------------
__global__ void hmm_prep_kernel(const float* __restrict__ log_trans) {
    size_t gtid = (size_t)blockIdx.x * blockDim.x + threadIdx.x;
    if (gtid < 2 * GRID) g_flag[gtid / GRID][gtid % GRID] = 0ull;
    const size_t n4 = (size_t)S * S / 4;
    const size_t stride = (size_t)gridDim.x * blockDim.x;
    for (size_t i = gtid; i < n4; i += stride) {
        float4 v = reinterpret_cast<const float4*>(log_trans)[i];
        __nv_bfloat162 lo, hi;
        lo.x = __float2bfloat16(__expf(v.x));
        lo.y = __float2bfloat16(__expf(v.y));
        hi.x = __float2bfloat16(__expf(v.z));
        hi.y = __float2bfloat16(__expf(v.w));
        reinterpret_cast<__nv_bfloat162*>(g_M)[2 * i]     = lo;
        reinterpret_cast<__nv_bfloat162*>(g_M)[2 * i + 1] = hi;
    }
}

// ---------------- helpers ----------------
__device__ __forceinline__ float warp_sum(float v) {
#pragma unroll
    for (int o = 16; o; o >>= 1) v += __shfl_xor_sync(0xffffffffu, v, o);
    return v;
}

// bf16x2 (u32) -> packed f32x2 (u64): exact
__device__ __forceinline__ unsigned long long cvt2(unsigned u) {
    unsigned lo = u << 16;
    unsigned hi = u & 0xffff0000u;
    unsigned long long r;
    asm("mov.b64 %0, {%1, %2};" : "=l"(r) : "r"(lo), "r"(hi));
    return r;
}

// packed dual FMA (FFMA2)
__device__ __forceinline__ unsigned long long fma2(unsigned long long a,
                                                   unsigned long long b,
                                                   unsigned long long c) {
    unsigned long long d;
    asm("fma.rn.f32x2 %0, %1, %2, %3;" : "=l"(d) : "l"(a), "l"(b), "l"(c));
    return d;
}

__device__ __forceinline__ float f32x2_hsum(unsigned long long v) {
    unsigned lo, hi;
    asm("mov.b64 {%0, %1}, %2;" : "=r"(lo), "=r"(hi) : "l"(v));
    return __uint_as_float(lo) + __uint_as_float(hi);
}

__device__ __forceinline__ unsigned long long ldacq(const unsigned long long* p) {
    unsigned long long v;
    asm volatile("ld.acquire.gpu.global.b64 %0, [%1];" : "=l"(v) : "l"(p) : "memory");
    return v;
}
__device__ __forceinline__ void strel(unsigned long long* p, unsigned long long v) {
    asm volatile("st.release.gpu.global.b64 [%0], %1;" :: "l"(p), "l"(v) : "memory");
}
__device__ __forceinline__ void strelax(float* p, float v) {
    asm volatile("st.relaxed.gpu.global.f32 [%0], %1;" :: "l"(p), "f"(v) : "memory");
}

// Barrier + Z-reduce in one hop — executed by WARP 0 ONLY (other warps park
// at __syncthreads with zero memory traffic; R3's all-warp spin flooded the
// L1tex queues chip-wide). Ping-pong slot makes exact-match spin safe: slot
// of gen is only rewritten at gen+2, which requires every block to have
// exited poll(gen) first. No atomics, no fences -> pinned L1 survives.
__device__ __forceinline__ float poll_flags(unsigned gen, int lane) {
    const unsigned long long* base = g_flag[gen & 1];
    unsigned long long x0, x1, x2, x3;
    for (;;) {
        x0 = ldacq(base + lane);
        x1 = ldacq(base + lane + 32);
        x2 = ldacq(base + lane + 64);
        x3 = ldacq(base + lane + 96);
        if (((unsigned)x0 == gen) & ((unsigned)x1 == gen) &
            ((unsigned)x2 == gen) & ((unsigned)x3 == gen)) break;
    }
    float zsum = __uint_as_float((unsigned)(x0 >> 32)) +
                 __uint_as_float((unsigned)(x1 >> 32)) +
                 __uint_as_float((unsigned)(x2 >> 32)) +
                 __uint_as_float((unsigned)(x3 >> 32));
    return warp_sum(zsum);
}

// dot products: 8 rows x 1024-wide K window against smem w
template <bool CACHED>
__device__ __forceinline__ void dot8(const uint4* __restrict__ A,
                                     const float* __restrict__ swq,
                                     int lane, unsigned long long* acc) {
#pragma unroll
    for (int c = 0; c < 4; ++c) {
        const int kb = c * 32 + lane;  // uint4 index in window
        const ulonglong2 w01 = *reinterpret_cast<const ulonglong2*>(swq + c * 256 + lane * 8);
        const ulonglong2 w23 = *reinterpret_cast<const ulonglong2*>(swq + c * 256 + lane * 8 + 4);
#pragma unroll
        for (int r = 0; r < 8; ++r) {
            uint4 a;
            if (CACHED) {
                a = A[r * ROWSTRIDE + kb];
            } else {
                float4 t = __ldcg(reinterpret_cast<const float4*>(A) + r * ROWSTRIDE + kb);
                a = *reinterpret_cast<uint4*>(&t);
            }
            acc[r] = fma2(cvt2(a.x), w01.x, acc[r]);
            acc[r] = fma2(cvt2(a.y), w01.y, acc[r]);
            acc[r] = fma2(cvt2(a.z), w23.x, acc[r]);
            acc[r] = fma2(cvt2(a.w), w23.y, acc[r]);
        }
    }
}

// ---------------- persistent forward-filter kernel ----------------
__global__ void __launch_bounds__(BLOCK, 1) hmm_main_kernel(
    const float* __restrict__ log_M0,
    const float* __restrict__ log_emit,
    const int*   __restrict__ Tptr,
    float*       __restrict__ out)
{
    __shared__ float sw[S];                       // current w (linear space)
    __shared__ __align__(16) float s_red[RPB][4]; // per-(row, K-quarter) partials

    const int tid  = threadIdx.x;
    const int lane = tid & 31;
    const int warp = tid >> 5;
    const int g    = warp >> 2;   // row group 0..3
    const int q    = warp & 3;    // K quarter 0..3
    const int bid  = blockIdx.x;
    const int T    = *Tptr;

    const int r0 = bid * RPB;                     // block's first global row
    const uint4* A = reinterpret_cast<const uint4*>(
        g_M + (size_t)(r0 + g * RPG) * S + q * KQ);
    const float* swq = sw + q * KQ;

    double lik = 0.0;
    float invZ = 0.f;

    // ---- t = 0: w0 = exp(log_M0 + log_emit[0]); only warp 0 works + polls ----
    if (warp == 0) {
        int row = r0 + lane;
        float v = __expf(__ldcg(log_M0 + row) + __ldcg(log_emit + row));
        strelax(&g_w[0][row], v);
        float part = warp_sum(v);
        __syncwarp();
        if (lane == 0)
            strel(&g_flag[1][bid],
                  ((unsigned long long)__float_as_uint(part) << 32) | 1u);
        float Z = poll_flags(1u, lane);           // gen 1 -> slot 1
        invZ = 1.0f / Z;
        if (bid == 0 && tid == 0) lik += (double)logf(Z);
    }
    __syncthreads();   // others wait for warp 0's poll (w0 globally visible)

    for (int t = 1; t <= T; ++t) {
        const int cur = t & 1, prev = cur ^ 1;
        const unsigned gen = (unsigned)(t + 1);

        // emit prefetch (independent; overlaps the sw broadcast)
        float em = 0.f;
        if (warp == 0) em = __ldcg(log_emit + (size_t)t * S + r0 + lane);

        // broadcast w_{t-1} into smem (each warp copies its 1/16 slice, L2-direct)
        {
            int j = warp * 64 + lane;
            float4 a = __ldcg(reinterpret_cast<const float4*>(g_w[prev]) + j);
            reinterpret_cast<float4*>(sw)[j] = a;
            j += 32;
            float4 b = __ldcg(reinterpret_cast<const float4*>(g_w[prev]) + j);
            reinterpret_cast<float4*>(sw)[j] = b;
        }
        __syncthreads();

        unsigned long long acc[8] = {0ull, 0ull, 0ull, 0ull, 0ull, 0ull, 0ull, 0ull};
        if (g < 3) dot8<true >(A, swq, lane, acc);
        else       dot8<false>(A, swq, lane, acc);

#pragma unroll
        for (int r = 0; r < 8; ++r) {
            float s = warp_sum(f32x2_hsum(acc[r]));
            if (lane == 0) s_red[g * RPG + r][q] = s;
        }
        __syncthreads();

        // epilogue + publish + barrier: warp 0 only; others park at bar.sync
        if (warp == 0) {
            float4 p = *reinterpret_cast<const float4*>(s_red[lane]);
            float dot = (p.x + p.y) + (p.z + p.w);
            float v = dot * __expf(em) * invZ;
            strelax(&g_w[cur][r0 + lane], v);
            float part = warp_sum(v);
            __syncwarp();
            if (lane == 0)
                strel(&g_flag[gen & 1][bid],
                      ((unsigned long long)__float_as_uint(part) << 32) | gen);
            float Z = poll_flags(gen, lane);
            invZ = 1.0f / Z;
            if (bid == 0 && tid == 0) lik += (double)logf(Z);
        }
        __syncthreads();
    }

    if (bid == 0 && tid == 0) out[0] = (float)lik;
}

// ---------------- launch ----------------
extern "C" void kernel_launch(void* const* d_in, const int* in_sizes, int n_in,
                              void* d_out, int out_size) {
    const float* log_M0    = (const float*)d_in[0];
    const float* log_trans = (const float*)d_in[1];
    const float* log_emit  = (const float*)d_in[2];
    const int*   Tptr      = (const int*)d_in[3];
    float* out = (float*)d_out;

    hmm_prep_kernel<<<2048, 256>>>(log_trans);
    hmm_main_kernel<<<GRID, BLOCK>>>(log_M0, log_emit, Tptr, out);
}